// round 6
// baseline (speedup 1.0000x reference)
#include <cuda_runtime.h>

#define NN 100000
#define EE 1600000
#define FH 32
#define SCAN_THREADS 1024
#define BINS_PER_THREAD 98   // 1024*98 = 100352 >= NN

// ---------------- device scratch (static; no allocations) ----------------
__device__ int g_idx64;                          // 1 if edge_index is int64
__device__ __align__(16) int   g_src[EE];
__device__ __align__(16) int   g_dst[EE];
__device__ __align__(16) unsigned long long g_edges[EE];  // packed {src(lo32), nw bits(hi32)}, bucketed by dst
__device__ __align__(16) float g_deg[NN];        // weighted out-degree, then dinv
__device__ __align__(16) int   g_cnt[NN];        // in-degree histogram
__device__ __align__(16) int   g_off[NN + 1];    // CSR offsets (by dst)
__device__ __align__(16) int   g_cursor[NN];     // bucket fill cursors
__device__ __align__(16) float g_aggx[NN * FH];  // agg(nw*x[src]) (stored by gate, reused by out)
__device__ __align__(16) float g_Z[NN * FH];
__device__ __align__(16) float g_HR[NN * FH];

// ---------------- kernels ----------------

// Probe edge_index dtype: true int64 indices are all < NN; int32 data read as
// u64 is >= 2^32 unless the odd word happens to be zero (~1e-5 per entry).
__global__ void detect_kernel(const void* ei) {
    const unsigned long long* p = (const unsigned long long*)ei;
    int is64 = 1;
    for (int i = 0; i < 16; i++)
        if (p[i] >= (unsigned long long)NN) is64 = 0;
    g_idx64 = is64;
}

__global__ void zero_kernel() {
    int i = blockIdx.x * blockDim.x + threadIdx.x;
    if (i < NN) {
        g_deg[i] = 0.f;
        g_cnt[i] = 0;
    }
}

// Pass A: convert indices, weighted out-degree (by src), in-degree histogram (by dst).
__global__ void passA_kernel(const void* ei, const float* __restrict__ ew) {
    int e = blockIdx.x * blockDim.x + threadIdx.x;
    if (e >= EE) return;
    int s, d;
    if (g_idx64) {
        const long long* p = (const long long*)ei;
        s = (int)p[e];
        d = (int)p[EE + e];
    } else {
        const int* p = (const int*)ei;
        s = p[e];
        d = p[EE + e];
    }
    g_src[e] = s;
    g_dst[e] = d;
    float w = (s == d) ? 0.f : ew[e];
    if (w != 0.f) atomicAdd(&g_deg[s], w);
    atomicAdd(&g_cnt[d], 1);
}

__global__ void dinv_kernel() {
    int i = blockIdx.x * blockDim.x + threadIdx.x;
    if (i >= NN) return;
    float dg = g_deg[i];
    g_deg[i] = (dg > 0.f) ? rsqrtf(fmaxf(dg, 1e-30f)) : 0.f;
}

// Single-block exclusive scan of g_cnt -> g_off (+ cursor copy, + g_off[NN]).
__global__ void __launch_bounds__(SCAN_THREADS) scan_kernel() {
    __shared__ int partial[SCAN_THREADS];
    int t = threadIdx.x;
    int begin = t * BINS_PER_THREAD;
    int end = min(begin + BINS_PER_THREAD, NN);
    int sum = 0;
    for (int i = begin; i < end; i++) sum += g_cnt[i];
    partial[t] = sum;
    __syncthreads();
    // Hillis-Steele inclusive scan
    for (int off = 1; off < SCAN_THREADS; off <<= 1) {
        int v = (t >= off) ? partial[t - off] : 0;
        __syncthreads();
        if (t >= off) partial[t] += v;
        __syncthreads();
    }
    int run = (t == 0) ? 0 : partial[t - 1];   // exclusive prefix
    for (int i = begin; i < end; i++) {
        int c = g_cnt[i];
        g_off[i] = run;
        g_cursor[i] = run;
        run += c;
    }
    if (t == SCAN_THREADS - 1) g_off[NN] = partial[SCAN_THREADS - 1];
}

// Pass B: compute normalized weight, bucket-scatter packed edge {src, nw}.
__global__ void passB_kernel(const float* __restrict__ ew) {
    int e = blockIdx.x * blockDim.x + threadIdx.x;
    if (e >= EE) return;
    int s = g_src[e];
    int d = g_dst[e];
    float w = (s == d) ? 0.f : ew[e];
    float nw = w * g_deg[s] * g_deg[d];
    int pos = atomicAdd(&g_cursor[d], 1);
    unsigned long long p = (unsigned)s |
        ((unsigned long long)__float_as_uint(nw) << 32);
    g_edges[pos] = p;
}

// Gate kernel: gathers ax = agg(nw*x[src]), ah = agg(nw*H[src]) per node
// (warp-per-node, lane = feature), stores ax for out_kernel reuse, then
// Z = sigmoid(chebZ), R = sigmoid(chebR), HR = H*R. W1 pre-negated in smem.
__global__ void __launch_bounds__(256) gate_kernel(
    const float* __restrict__ x, const float* __restrict__ H,
    const float* __restrict__ Wxz, const float* __restrict__ bxz,
    const float* __restrict__ Whz, const float* __restrict__ bhz,
    const float* __restrict__ Wxr, const float* __restrict__ bxr,
    const float* __restrict__ Whr, const float* __restrict__ bhr) {
    __shared__ float sW[8 * 1024];
    __shared__ float sbz[32];
    __shared__ float sbr[32];

    const float* mats[4] = {Wxz, Whz, Wxr, Whr};
    for (int i = threadIdx.x; i < 8 * 1024; i += blockDim.x) {
        int m = i >> 10;        // [Wxz0,Wxz1, Whz0,Whz1, Wxr0,Wxr1, Whr0,Whr1]
        int r = i & 1023;
        float v = mats[m >> 1][(m & 1) * 1024 + r];
        sW[i] = (m & 1) ? -v : v;   // fold tx1 = -agg into W1
    }
    if (threadIdx.x < 32) {
        sbz[threadIdx.x] = bxz[threadIdx.x] + bhz[threadIdx.x];
        sbr[threadIdx.x] = bxr[threadIdx.x] + bhr[threadIdx.x];
    }
    __syncthreads();

    int node = blockIdx.x * 8 + (threadIdx.x >> 5);
    if (node >= NN) return;
    int lane = threadIdx.x & 31;
    size_t base = (size_t)node * FH + lane;

    // ---- gather phase (no atomics) ----
    int beg = g_off[node];
    int end = g_off[node + 1];
    float ax = 0.f, ah = 0.f;
    for (int j = beg; j < end; j++) {
        unsigned long long p = g_edges[j];
        int s = (int)(unsigned)p;
        float wv = __uint_as_float((unsigned)(p >> 32));
        size_t sb = (size_t)s * FH + lane;
        ax = fmaf(wv, __ldg(x + sb), ax);
        ah = fmaf(wv, __ldg(H + sb), ah);
    }
    g_aggx[base] = ax;

    float xv = x[base];
    float hv = H[base];
    float az = sbz[lane];
    float ar = sbr[lane];

#pragma unroll
    for (int k = 0; k < 32; k++) {
        float xs  = __shfl_sync(0xffffffffu, xv, k);
        float axs = __shfl_sync(0xffffffffu, ax, k);
        float hs  = __shfl_sync(0xffffffffu, hv, k);
        float ahs = __shfl_sync(0xffffffffu, ah, k);
        int o = k * 32 + lane;
        az = fmaf(xs,  sW[o],        az);
        az = fmaf(axs, sW[1024 + o], az);
        az = fmaf(hs,  sW[2048 + o], az);
        az = fmaf(ahs, sW[3072 + o], az);
        ar = fmaf(xs,  sW[4096 + o], ar);
        ar = fmaf(axs, sW[5120 + o], ar);
        ar = fmaf(hs,  sW[6144 + o], ar);
        ar = fmaf(ahs, sW[7168 + o], ar);
    }
    float z = 1.f / (1.f + __expf(-az));
    float r = 1.f / (1.f + __expf(-ar));
    g_Z[base]  = z;
    g_HR[base] = hv * r;
}

// Out kernel: gathers ahr = agg(nw*HR[src]) per node, then
// H_tilde = tanh(chebH), h = Z*H + (1-Z)*H_tilde, out = relu(h)@lin_w + lin_b.
__global__ void __launch_bounds__(256) out_kernel(
    const float* __restrict__ x, const float* __restrict__ H,
    const float* __restrict__ Wxh, const float* __restrict__ bxh,
    const float* __restrict__ Whh, const float* __restrict__ bhh,
    const float* __restrict__ lw, const float* __restrict__ lb,
    float* __restrict__ out, int out_size) {
    __shared__ float sW[4 * 1024];
    __shared__ float sbh[32];
    __shared__ float slw[128];
    __shared__ float slb[4];

    for (int i = threadIdx.x; i < 4 * 1024; i += blockDim.x) {
        int m = i >> 10;        // [Wxh0,Wxh1, Whh0,Whh1]
        int r = i & 1023;
        const float* Wp = (m < 2) ? Wxh : Whh;
        float v = Wp[(m & 1) * 1024 + r];
        sW[i] = (m & 1) ? -v : v;
    }
    if (threadIdx.x < 32) sbh[threadIdx.x] = bxh[threadIdx.x] + bhh[threadIdx.x];
    if (threadIdx.x < 128) slw[threadIdx.x] = lw[threadIdx.x];
    if (threadIdx.x < 4) slb[threadIdx.x] = lb[threadIdx.x];
    __syncthreads();

    int node = blockIdx.x * 8 + (threadIdx.x >> 5);
    if (node >= NN) return;
    int lane = threadIdx.x & 31;
    size_t base = (size_t)node * FH + lane;

    // ---- gather phase on HR ----
    int beg = g_off[node];
    int end = g_off[node + 1];
    float ahr = 0.f;
    for (int j = beg; j < end; j++) {
        unsigned long long p = g_edges[j];
        int s = (int)(unsigned)p;
        float wv = __uint_as_float((unsigned)(p >> 32));
        ahr = fmaf(wv, __ldg(g_HR + (size_t)s * FH + lane), ahr);
    }

    float xv  = x[base];
    float hrv = g_HR[base];
    float ax  = g_aggx[base];
    float a = sbh[lane];

#pragma unroll
    for (int k = 0; k < 32; k++) {
        float xs  = __shfl_sync(0xffffffffu, xv, k);
        float axs = __shfl_sync(0xffffffffu, ax, k);
        float hs  = __shfl_sync(0xffffffffu, hrv, k);
        float ahs = __shfl_sync(0xffffffffu, ahr, k);
        int o = k * 32 + lane;
        a = fmaf(xs,  sW[o],        a);
        a = fmaf(axs, sW[1024 + o], a);
        a = fmaf(hs,  sW[2048 + o], a);
        a = fmaf(ahs, sW[3072 + o], a);
    }
    float ht = tanhf(a);
    float z = g_Z[base];
    float hval = z * H[base] + (1.f - z) * ht;

    long long hidx = (long long)NN * 4 + (long long)base;
    if (hidx < (long long)out_size) out[hidx] = hval;

    float rh = fmaxf(hval, 0.f);
#pragma unroll
    for (int j = 0; j < 4; j++) {
        float s = rh * slw[lane * 4 + j];
#pragma unroll
        for (int off = 16; off; off >>= 1) s += __shfl_xor_sync(0xffffffffu, s, off);
        if (lane == 0 && (long long)node * 4 + j < (long long)out_size)
            out[(size_t)node * 4 + j] = s + slb[j];
    }
}

// ---------------- launch ----------------
extern "C" void kernel_launch(void* const* d_in, const int* in_sizes, int n_in,
                              void* d_out, int out_size) {
    const float* x   = (const float*)d_in[0];
    const void*  ei  = d_in[1];
    const float* ew  = (const float*)d_in[2];
    const float* H   = (const float*)d_in[3];
    const float* Wxz = (const float*)d_in[4];
    const float* bxz = (const float*)d_in[5];
    const float* Whz = (const float*)d_in[6];
    const float* bhz = (const float*)d_in[7];
    const float* Wxr = (const float*)d_in[8];
    const float* bxr = (const float*)d_in[9];
    const float* Whr = (const float*)d_in[10];
    const float* bhr = (const float*)d_in[11];
    const float* Wxh = (const float*)d_in[12];
    const float* bxh = (const float*)d_in[13];
    const float* Whh = (const float*)d_in[14];
    const float* bhh = (const float*)d_in[15];
    const float* lw  = (const float*)d_in[16];
    const float* lb  = (const float*)d_in[17];
    float* out = (float*)d_out;

    detect_kernel<<<1, 1>>>(ei);
    zero_kernel<<<(NN + 255) / 256, 256>>>();
    passA_kernel<<<(EE + 255) / 256, 256>>>(ei, ew);
    dinv_kernel<<<(NN + 255) / 256, 256>>>();
    scan_kernel<<<1, SCAN_THREADS>>>();
    passB_kernel<<<(EE + 255) / 256, 256>>>(ew);
    gate_kernel<<<(NN + 7) / 8, 256>>>(x, H, Wxz, bxz, Whz, bhz, Wxr, bxr, Whr, bhr);
    out_kernel<<<(NN + 7) / 8, 256>>>(x, H, Wxh, bxh, Whh, bhh, lw, lb, out, out_size);
}

// round 7
// speedup vs baseline: 1.8125x; 1.8125x over previous
#include <cuda_runtime.h>

#define NN 100000
#define EE 1600000
#define FH 32
typedef unsigned long long ULL;

// ---------------- device scratch (static; no allocations) ----------------
__device__ int g_idx64;                          // 1 if edge_index is int64
__device__ __align__(16) int   g_src[EE];
__device__ __align__(16) int   g_dst[EE];
__device__ __align__(16) float g_deg[NN];        // weighted out-degree, then dinv
__device__ __align__(16) float g_nw[EE];         // per-edge sym-normalized weight
__device__ __align__(16) float g_aggx[NN * FH];  // agg(nw*x[src]) by dst
__device__ __align__(16) float g_aggh[NN * FH];  // agg(nw*H[src]) by dst
__device__ __align__(16) float g_agghr[NN * FH]; // agg(nw*(H*R)[src]) by dst
__device__ __align__(16) float g_Z[NN * FH];
__device__ __align__(16) float g_HR[NN * FH];

__device__ __forceinline__ void red_add_v4(float* addr, float a, float b, float c, float d) {
    asm volatile("red.global.add.v4.f32 [%0], {%1, %2, %3, %4};"
                 :: "l"(addr), "f"(a), "f"(b), "f"(c), "f"(d)
                 : "memory");
}
// packed fp32x2 helpers (exact fp32 lanewise)
__device__ __forceinline__ ULL fma2(ULL a, ULL b, ULL c) {
    ULL d;
    asm("fma.rn.f32x2 %0, %1, %2, %3;" : "=l"(d) : "l"(a), "l"(b), "l"(c));
    return d;
}
__device__ __forceinline__ ULL dup2(float w) {
    ULL d; unsigned u = __float_as_uint(w);
    asm("mov.b64 %0, {%1, %2};" : "=l"(d) : "r"(u), "r"(u));
    return d;
}
__device__ __forceinline__ float lo2(ULL v) { return __uint_as_float((unsigned)v); }
__device__ __forceinline__ float hi2(ULL v) { return __uint_as_float((unsigned)(v >> 32)); }

// ---------------- kernels ----------------

// init: dtype probe (thread 0) + zero agg arrays and deg.
__global__ void init_kernel(const void* ei) {
    int i = blockIdx.x * blockDim.x + threadIdx.x;
    if (i == 0) {
        const ULL* p = (const ULL*)ei;
        int is64 = 1;
        for (int k = 0; k < 16; k++)
            if (p[k] >= (ULL)NN) is64 = 0;
        g_idx64 = is64;
    }
    if (i < NN) g_deg[i] = 0.f;
    if (i < NN * FH) { g_aggx[i] = 0.f; g_aggh[i] = 0.f; g_agghr[i] = 0.f; }
}

// convert indices to int32 + weighted out-degree.
__global__ void passA_kernel(const void* ei, const float* __restrict__ ew) {
    int e = blockIdx.x * blockDim.x + threadIdx.x;
    if (e >= EE) return;
    int s, d;
    if (g_idx64) {
        const long long* p = (const long long*)ei;
        s = (int)p[e]; d = (int)p[EE + e];
    } else {
        const int* p = (const int*)ei;
        s = p[e]; d = p[EE + e];
    }
    g_src[e] = s;
    g_dst[e] = d;
    float w = (s == d) ? 0.f : ew[e];
    if (w != 0.f) atomicAdd(&g_deg[s], w);
}

__global__ void dinv_kernel() {
    int i = blockIdx.x * blockDim.x + threadIdx.x;
    if (i >= NN) return;
    float dg = g_deg[i];
    g_deg[i] = (dg > 0.f) ? rsqrtf(fmaxf(dg, 1e-30f)) : 0.f;
}

// Fused scatter of x and H with inline nw: 8 threads/edge, leader computes nw.
__global__ void scatter_xh_kernel(const float* __restrict__ x,
                                  const float* __restrict__ H,
                                  const float* __restrict__ ew) {
    unsigned t = blockIdx.x * blockDim.x + threadIdx.x;
    int e = (int)(t >> 3);
    if (e >= EE) return;
    int lane8 = (int)t & 7;
    int s = g_src[e];
    int d = g_dst[e];
    float nw = 0.f;
    if (lane8 == 0) {
        float w = (s == d) ? 0.f : ew[e];
        nw = w * g_deg[s] * g_deg[d];
        g_nw[e] = nw;
    }
    nw = __shfl_sync(0xffffffffu, nw, threadIdx.x & 24);
    if (nw == 0.f) return;
    int f = lane8 * 4;
    const float4 xv = *(const float4*)(x + (size_t)s * FH + f);
    red_add_v4(g_aggx + (size_t)d * FH + f, nw * xv.x, nw * xv.y, nw * xv.z, nw * xv.w);
    const float4 hv = *(const float4*)(H + (size_t)s * FH + f);
    red_add_v4(g_aggh + (size_t)d * FH + f, nw * hv.x, nw * hv.y, nw * hv.z, nw * hv.w);
}

__global__ void scatter_hr_kernel() {
    unsigned t = blockIdx.x * blockDim.x + threadIdx.x;
    int e = (int)(t >> 3);
    if (e >= EE) return;
    int f = ((int)t & 7) * 4;
    float nw = g_nw[e];
    if (nw == 0.f) return;
    int s = g_src[e];
    int d = g_dst[e];
    const float4 hv = *(const float4*)(g_HR + (size_t)s * FH + f);
    red_add_v4(g_agghr + (size_t)d * FH + f, nw * hv.x, nw * hv.y, nw * hv.z, nw * hv.w);
}

// ---------------- gate GEMM: 4 nodes per warp, f32x2 ----------------
// dynamic smem layout (floats): sW[8192] | sIn[32*132] | sbz[32] | sbr[32]
#define GATE_SMEM_FLOATS (8192 + 32 * 132 + 64)
__global__ void __launch_bounds__(256) gate_kernel(
    const float* __restrict__ x, const float* __restrict__ H,
    const float* __restrict__ Wxz, const float* __restrict__ bxz,
    const float* __restrict__ Whz, const float* __restrict__ bhz,
    const float* __restrict__ Wxr, const float* __restrict__ bxr,
    const float* __restrict__ Whr, const float* __restrict__ bhr) {
    extern __shared__ __align__(16) float dyn[];
    float* sW   = dyn;                 // 8 mats: [Wxz0,-Wxz1, Whz0,-Whz1, Wxr0,-Wxr1, Whr0,-Whr1]
    float* sInF = dyn + 8192;          // [k][m*32 + pair*2 + sub], row pad 132
    float* sbz  = dyn + 8192 + 32 * 132;
    float* sbr  = sbz + 32;

    const float* mats[4] = {Wxz, Whz, Wxr, Whr};
    for (int i = threadIdx.x; i < 8 * 1024; i += blockDim.x) {
        int m = i >> 10;
        int r = i & 1023;
        float v = mats[m >> 1][(m & 1) * 1024 + r];
        sW[i] = (m & 1) ? -v : v;
    }
    if (threadIdx.x < 32) {
        sbz[threadIdx.x] = bxz[threadIdx.x] + bhz[threadIdx.x];
        sbr[threadIdx.x] = bxr[threadIdx.x] + bhr[threadIdx.x];
    }
    __syncthreads();

    int w = threadIdx.x >> 5;
    int lane = threadIdx.x & 31;
    int nbase = blockIdx.x * 32 + w * 4;

    // phase 1: stage inputs [x, aggx, H, aggh] per feature-row
#pragma unroll
    for (int i = 0; i < 4; i++) {
        size_t b = (size_t)(nbase + i) * FH + lane;
        int off = lane * 132 + (w * 2 + (i >> 1)) * 2 + (i & 1);
        sInF[off]      = x[b];
        sInF[off + 32] = g_aggx[b];
        sInF[off + 64] = H[b];
        sInF[off + 96] = g_aggh[b];
    }
    __syncwarp();

    ULL az0 = dup2(sbz[lane]), az1 = az0;
    ULL ar0 = dup2(sbr[lane]), ar1 = ar0;
    int p0 = w * 2, p1 = w * 2 + 1;

#pragma unroll
    for (int k = 0; k < 32; k++) {
        const float* wrow = sW + k * 32 + lane;
        ULL w0 = dup2(wrow[0]);
        ULL w1 = dup2(wrow[1024]);
        ULL w2 = dup2(wrow[2048]);
        ULL w3 = dup2(wrow[3072]);
        ULL w4 = dup2(wrow[4096]);
        ULL w5 = dup2(wrow[5120]);
        ULL w6 = dup2(wrow[6144]);
        ULL w7 = dup2(wrow[7168]);
        const ULL* inrow = (const ULL*)(sInF + k * 132);
        ULL x0 = inrow[p0],      x1 = inrow[p1];
        ULL a0 = inrow[16 + p0], a1 = inrow[16 + p1];
        ULL h0 = inrow[32 + p0], h1 = inrow[32 + p1];
        ULL g0 = inrow[48 + p0], g1 = inrow[48 + p1];
        az0 = fma2(x0, w0, az0); az0 = fma2(a0, w1, az0);
        az0 = fma2(h0, w2, az0); az0 = fma2(g0, w3, az0);
        az1 = fma2(x1, w0, az1); az1 = fma2(a1, w1, az1);
        az1 = fma2(h1, w2, az1); az1 = fma2(g1, w3, az1);
        ar0 = fma2(x0, w4, ar0); ar0 = fma2(a0, w5, ar0);
        ar0 = fma2(h0, w6, ar0); ar0 = fma2(g0, w7, ar0);
        ar1 = fma2(x1, w4, ar1); ar1 = fma2(a1, w5, ar1);
        ar1 = fma2(h1, w6, ar1); ar1 = fma2(g1, w7, ar1);
    }

    float zp[4] = {lo2(az0), hi2(az0), lo2(az1), hi2(az1)};
    float rp[4] = {lo2(ar0), hi2(ar0), lo2(ar1), hi2(ar1)};
#pragma unroll
    for (int i = 0; i < 4; i++) {
        size_t b = (size_t)(nbase + i) * FH + lane;
        float z = 1.f / (1.f + __expf(-zp[i]));
        float r = 1.f / (1.f + __expf(-rp[i]));
        float hv = sInF[lane * 132 + 64 + (w * 2 + (i >> 1)) * 2 + (i & 1)];
        g_Z[b]  = z;
        g_HR[b] = hv * r;
    }
}

// ---------------- out GEMM: 4 nodes per warp, f32x2 ----------------
__global__ void __launch_bounds__(256) out_kernel(
    const float* __restrict__ x, const float* __restrict__ H,
    const float* __restrict__ Wxh, const float* __restrict__ bxh,
    const float* __restrict__ Whh, const float* __restrict__ bhh,
    const float* __restrict__ lw, const float* __restrict__ lb,
    float* __restrict__ out, int out_size) {
    __shared__ float sW[4 * 1024];         // [Wxh0, -Wxh1, Whh0, -Whh1]
    __shared__ __align__(16) float sInF[32 * 132];
    __shared__ float sbh[32];
    __shared__ float slw[128];
    __shared__ float slb[4];

    for (int i = threadIdx.x; i < 4 * 1024; i += blockDim.x) {
        int m = i >> 10;
        int r = i & 1023;
        const float* Wp = (m < 2) ? Wxh : Whh;
        float v = Wp[(m & 1) * 1024 + r];
        sW[i] = (m & 1) ? -v : v;
    }
    if (threadIdx.x < 32) sbh[threadIdx.x] = bxh[threadIdx.x] + bhh[threadIdx.x];
    if (threadIdx.x < 128) slw[threadIdx.x] = lw[threadIdx.x];
    if (threadIdx.x < 4) slb[threadIdx.x] = lb[threadIdx.x];
    __syncthreads();

    int w = threadIdx.x >> 5;
    int lane = threadIdx.x & 31;
    int nbase = blockIdx.x * 32 + w * 4;

    // phase 1: stage inputs [x, aggx, HR, aggHR]
#pragma unroll
    for (int i = 0; i < 4; i++) {
        size_t b = (size_t)(nbase + i) * FH + lane;
        int off = lane * 132 + (w * 2 + (i >> 1)) * 2 + (i & 1);
        sInF[off]      = x[b];
        sInF[off + 32] = g_aggx[b];
        sInF[off + 64] = g_HR[b];
        sInF[off + 96] = g_agghr[b];
    }
    __syncwarp();

    ULL a0acc = dup2(sbh[lane]), a1acc = a0acc;
    int p0 = w * 2, p1 = w * 2 + 1;

#pragma unroll
    for (int k = 0; k < 32; k++) {
        const float* wrow = sW + k * 32 + lane;
        ULL w0 = dup2(wrow[0]);
        ULL w1 = dup2(wrow[1024]);
        ULL w2 = dup2(wrow[2048]);
        ULL w3 = dup2(wrow[3072]);
        const ULL* inrow = (const ULL*)(sInF + k * 132);
        ULL x0 = inrow[p0],      x1 = inrow[p1];
        ULL a0 = inrow[16 + p0], a1 = inrow[16 + p1];
        ULL h0 = inrow[32 + p0], h1 = inrow[32 + p1];
        ULL g0 = inrow[48 + p0], g1 = inrow[48 + p1];
        a0acc = fma2(x0, w0, a0acc); a0acc = fma2(a0, w1, a0acc);
        a0acc = fma2(h0, w2, a0acc); a0acc = fma2(g0, w3, a0acc);
        a1acc = fma2(x1, w0, a1acc); a1acc = fma2(a1, w1, a1acc);
        a1acc = fma2(h1, w2, a1acc); a1acc = fma2(g1, w3, a1acc);
    }

    float ap[4] = {lo2(a0acc), hi2(a0acc), lo2(a1acc), hi2(a1acc)};
#pragma unroll
    for (int i = 0; i < 4; i++) {
        int node = nbase + i;
        size_t b = (size_t)node * FH + lane;
        float ht = tanhf(ap[i]);
        float z = g_Z[b];
        float hval = z * H[b] + (1.f - z) * ht;

        long long hidx = (long long)NN * 4 + (long long)b;
        if (hidx < (long long)out_size) out[hidx] = hval;

        float rh = fmaxf(hval, 0.f);
#pragma unroll
        for (int j = 0; j < 4; j++) {
            float s = rh * slw[lane * 4 + j];
#pragma unroll
            for (int off = 16; off; off >>= 1) s += __shfl_xor_sync(0xffffffffu, s, off);
            if (lane == 0 && (long long)node * 4 + j < (long long)out_size)
                out[(size_t)node * 4 + j] = s + slb[j];
        }
    }
}

// ---------------- launch ----------------
extern "C" void kernel_launch(void* const* d_in, const int* in_sizes, int n_in,
                              void* d_out, int out_size) {
    const float* x   = (const float*)d_in[0];
    const void*  ei  = d_in[1];
    const float* ew  = (const float*)d_in[2];
    const float* H   = (const float*)d_in[3];
    const float* Wxz = (const float*)d_in[4];
    const float* bxz = (const float*)d_in[5];
    const float* Whz = (const float*)d_in[6];
    const float* bhz = (const float*)d_in[7];
    const float* Wxr = (const float*)d_in[8];
    const float* bxr = (const float*)d_in[9];
    const float* Whr = (const float*)d_in[10];
    const float* bhr = (const float*)d_in[11];
    const float* Wxh = (const float*)d_in[12];
    const float* bxh = (const float*)d_in[13];
    const float* Whh = (const float*)d_in[14];
    const float* bhh = (const float*)d_in[15];
    const float* lw  = (const float*)d_in[16];
    const float* lb  = (const float*)d_in[17];
    float* out = (float*)d_out;

    static int smem_set = 0;
    if (!smem_set) {
        cudaFuncSetAttribute(gate_kernel, cudaFuncAttributeMaxDynamicSharedMemorySize,
                             GATE_SMEM_FLOATS * 4);
        smem_set = 1;
    }

    init_kernel<<<(NN * FH + 255) / 256, 256>>>(ei);
    passA_kernel<<<(EE + 255) / 256, 256>>>(ei, ew);
    dinv_kernel<<<(NN + 255) / 256, 256>>>();
    scatter_xh_kernel<<<(EE * 8 + 255) / 256, 256>>>(x, H, ew);
    gate_kernel<<<(NN + 31) / 32, 256, GATE_SMEM_FLOATS * 4>>>(
        x, H, Wxz, bxz, Whz, bhz, Wxr, bxr, Whr, bhr);
    scatter_hr_kernel<<<(EE * 8 + 255) / 256, 256>>>();
    out_kernel<<<(NN + 31) / 32, 256>>>(x, H, Wxh, bxh, Whh, bhh, lw, lb, out, out_size);
}

// round 8
// speedup vs baseline: 1.9898x; 1.0978x over previous
#include <cuda_runtime.h>
#include <cuda_fp16.h>

#define NN 100000
#define EE 1600000
#define FH 32
typedef unsigned long long ULL;

// ---------------- device scratch (static; no allocations) ----------------
__device__ int g_idx64;                          // 1 if edge_index is int64
__device__ __align__(16) int    g_src[EE];
__device__ __align__(16) int    g_dst[EE];
__device__ __align__(16) float  g_deg[NN];       // weighted out-degree, then dinv
__device__ __align__(16) float  g_nw[EE];        // per-edge sym-normalized weight
__device__ __align__(16) __half g_x16[NN * FH];  // fp16 copy of x (gather source)
__device__ __align__(16) __half g_h16[NN * FH];  // fp16 copy of H
__device__ __align__(16) __half g_hr16[NN * FH]; // fp16 copy of H*R
__device__ __align__(16) float  g_aggx[NN * FH]; // agg(nw*x[src]) by dst (fp32 accum)
__device__ __align__(16) float  g_aggh[NN * FH];
__device__ __align__(16) float  g_agghr[NN * FH];
__device__ __align__(16) float  g_Z[NN * FH];
__device__ __align__(16) float  g_HR[NN * FH];   // fp32 H*R (out-GEMM input)

__device__ __forceinline__ void red_add_v4(float* addr, float a, float b, float c, float d) {
    asm volatile("red.global.add.v4.f32 [%0], {%1, %2, %3, %4};"
                 :: "l"(addr), "f"(a), "f"(b), "f"(c), "f"(d)
                 : "memory");
}
// packed fp32x2 helpers (exact fp32 lanewise)
__device__ __forceinline__ ULL fma2(ULL a, ULL b, ULL c) {
    ULL d;
    asm("fma.rn.f32x2 %0, %1, %2, %3;" : "=l"(d) : "l"(a), "l"(b), "l"(c));
    return d;
}
__device__ __forceinline__ ULL dup2(float w) {
    ULL d; unsigned u = __float_as_uint(w);
    asm("mov.b64 %0, {%1, %2};" : "=l"(d) : "r"(u), "r"(u));
    return d;
}
__device__ __forceinline__ float lo2(ULL v) { return __uint_as_float((unsigned)v); }
__device__ __forceinline__ float hi2(ULL v) { return __uint_as_float((unsigned)(v >> 32)); }

// ---------------- kernels ----------------

// init: dtype probe + zero deg/aggs + pack x,H to fp16.
__global__ void init_kernel(const void* ei, const float* __restrict__ x,
                            const float* __restrict__ H) {
    int i = blockIdx.x * blockDim.x + threadIdx.x;
    if (i == 0) {
        const ULL* p = (const ULL*)ei;
        int is64 = 1;
        for (int k = 0; k < 16; k++)
            if (p[k] >= (ULL)NN) is64 = 0;
        g_idx64 = is64;
    }
    if (i < NN) g_deg[i] = 0.f;
    if (i < NN * FH) { g_aggx[i] = 0.f; g_aggh[i] = 0.f; g_agghr[i] = 0.f; }
    if (i < NN * 8) {
        int off = i * 4;
        float4 xv = *(const float4*)(x + off);
        float4 hv = *(const float4*)(H + off);
        __half2 xa = __floats2half2_rn(xv.x, xv.y);
        __half2 xb = __floats2half2_rn(xv.z, xv.w);
        __half2 ha = __floats2half2_rn(hv.x, hv.y);
        __half2 hb = __floats2half2_rn(hv.z, hv.w);
        *(__half2*)(g_x16 + off)     = xa;
        *(__half2*)(g_x16 + off + 2) = xb;
        *(__half2*)(g_h16 + off)     = ha;
        *(__half2*)(g_h16 + off + 2) = hb;
    }
}

// convert indices to int32 + weighted out-degree.
__global__ void passA_kernel(const void* ei, const float* __restrict__ ew) {
    int e = blockIdx.x * blockDim.x + threadIdx.x;
    if (e >= EE) return;
    int s, d;
    if (g_idx64) {
        const long long* p = (const long long*)ei;
        s = (int)p[e]; d = (int)p[EE + e];
    } else {
        const int* p = (const int*)ei;
        s = p[e]; d = p[EE + e];
    }
    g_src[e] = s;
    g_dst[e] = d;
    float w = (s == d) ? 0.f : ew[e];
    if (w != 0.f) atomicAdd(&g_deg[s], w);
}

__global__ void dinv_kernel() {
    int i = blockIdx.x * blockDim.x + threadIdx.x;
    if (i >= NN) return;
    float dg = g_deg[i];
    g_deg[i] = (dg > 0.f) ? rsqrtf(fmaxf(dg, 1e-30f)) : 0.f;
}

// Fused scatter of x and H, 2 edges per 8-thread group, fp16 gathers.
__global__ void scatter_xh_kernel(const float* __restrict__ ew) {
    unsigned t = blockIdx.x * blockDim.x + threadIdx.x;
    int g = (int)(t >> 3);
    int e0 = g * 2;
    if (e0 >= EE) return;
    int q = (int)t & 7;
    int2 s2 = *(const int2*)(g_src + e0);
    int2 d2 = *(const int2*)(g_dst + e0);
    float nw0 = 0.f, nw1 = 0.f;
    if (q == 0) {
        float2 w2 = *(const float2*)(ew + e0);
        float w0 = (s2.x == d2.x) ? 0.f : w2.x;
        float w1 = (s2.y == d2.y) ? 0.f : w2.y;
        nw0 = w0 * g_deg[s2.x] * g_deg[d2.x];
        nw1 = w1 * g_deg[s2.y] * g_deg[d2.y];
        *(float2*)(g_nw + e0) = make_float2(nw0, nw1);
    }
    int srcl = threadIdx.x & 24;
    nw0 = __shfl_sync(0xffffffffu, nw0, srcl);
    nw1 = __shfl_sync(0xffffffffu, nw1, srcl);
    int f = q * 4;
    // front-batched loads for MLP
    uint2 xp0, hp0, xp1, hp1;
    if (nw0 != 0.f) {
        xp0 = *(const uint2*)(g_x16 + s2.x * FH + f);
        hp0 = *(const uint2*)(g_h16 + s2.x * FH + f);
    }
    if (nw1 != 0.f) {
        xp1 = *(const uint2*)(g_x16 + s2.y * FH + f);
        hp1 = *(const uint2*)(g_h16 + s2.y * FH + f);
    }
    if (nw0 != 0.f) {
        float2 a = __half22float2(*(__half2*)&xp0.x);
        float2 b = __half22float2(*(__half2*)&xp0.y);
        red_add_v4(g_aggx + d2.x * FH + f, nw0 * a.x, nw0 * a.y, nw0 * b.x, nw0 * b.y);
        float2 c = __half22float2(*(__half2*)&hp0.x);
        float2 e = __half22float2(*(__half2*)&hp0.y);
        red_add_v4(g_aggh + d2.x * FH + f, nw0 * c.x, nw0 * c.y, nw0 * e.x, nw0 * e.y);
    }
    if (nw1 != 0.f) {
        float2 a = __half22float2(*(__half2*)&xp1.x);
        float2 b = __half22float2(*(__half2*)&xp1.y);
        red_add_v4(g_aggx + d2.y * FH + f, nw1 * a.x, nw1 * a.y, nw1 * b.x, nw1 * b.y);
        float2 c = __half22float2(*(__half2*)&hp1.x);
        float2 e = __half22float2(*(__half2*)&hp1.y);
        red_add_v4(g_aggh + d2.y * FH + f, nw1 * c.x, nw1 * c.y, nw1 * e.x, nw1 * e.y);
    }
}

// Scatter of H*R (fp16 gathers), 2 edges per 8-thread group.
__global__ void scatter_hr_kernel() {
    unsigned t = blockIdx.x * blockDim.x + threadIdx.x;
    int g = (int)(t >> 3);
    int e0 = g * 2;
    if (e0 >= EE) return;
    int q = (int)t & 7;
    float2 nw2 = *(const float2*)(g_nw + e0);
    int2 s2 = *(const int2*)(g_src + e0);
    int2 d2 = *(const int2*)(g_dst + e0);
    int f = q * 4;
    uint2 p0, p1;
    if (nw2.x != 0.f) p0 = *(const uint2*)(g_hr16 + s2.x * FH + f);
    if (nw2.y != 0.f) p1 = *(const uint2*)(g_hr16 + s2.y * FH + f);
    if (nw2.x != 0.f) {
        float2 a = __half22float2(*(__half2*)&p0.x);
        float2 b = __half22float2(*(__half2*)&p0.y);
        red_add_v4(g_agghr + d2.x * FH + f, nw2.x * a.x, nw2.x * a.y, nw2.x * b.x, nw2.x * b.y);
    }
    if (nw2.y != 0.f) {
        float2 a = __half22float2(*(__half2*)&p1.x);
        float2 b = __half22float2(*(__half2*)&p1.y);
        red_add_v4(g_agghr + d2.y * FH + f, nw2.y * a.x, nw2.y * a.y, nw2.y * b.x, nw2.y * b.y);
    }
}

// ---------------- gate GEMM: 4 nodes per warp, f32x2 ----------------
#define GATE_SMEM_FLOATS (8192 + 32 * 132 + 64)
__global__ void __launch_bounds__(256) gate_kernel(
    const float* __restrict__ x, const float* __restrict__ H,
    const float* __restrict__ Wxz, const float* __restrict__ bxz,
    const float* __restrict__ Whz, const float* __restrict__ bhz,
    const float* __restrict__ Wxr, const float* __restrict__ bxr,
    const float* __restrict__ Whr, const float* __restrict__ bhr) {
    extern __shared__ __align__(16) float dyn[];
    float* sW   = dyn;                 // [Wxz0,-Wxz1, Whz0,-Whz1, Wxr0,-Wxr1, Whr0,-Whr1]
    float* sInF = dyn + 8192;
    float* sbz  = dyn + 8192 + 32 * 132;
    float* sbr  = sbz + 32;

    const float* mats[4] = {Wxz, Whz, Wxr, Whr};
    for (int i = threadIdx.x; i < 8 * 1024; i += blockDim.x) {
        int m = i >> 10;
        int r = i & 1023;
        float v = mats[m >> 1][(m & 1) * 1024 + r];
        sW[i] = (m & 1) ? -v : v;
    }
    if (threadIdx.x < 32) {
        sbz[threadIdx.x] = bxz[threadIdx.x] + bhz[threadIdx.x];
        sbr[threadIdx.x] = bxr[threadIdx.x] + bhr[threadIdx.x];
    }
    __syncthreads();

    int w = threadIdx.x >> 5;
    int lane = threadIdx.x & 31;
    int nbase = blockIdx.x * 32 + w * 4;

#pragma unroll
    for (int i = 0; i < 4; i++) {
        size_t b = (size_t)(nbase + i) * FH + lane;
        int off = lane * 132 + (w * 2 + (i >> 1)) * 2 + (i & 1);
        sInF[off]      = x[b];
        sInF[off + 32] = g_aggx[b];
        sInF[off + 64] = H[b];
        sInF[off + 96] = g_aggh[b];
    }
    __syncwarp();

    ULL az0 = dup2(sbz[lane]), az1 = az0;
    ULL ar0 = dup2(sbr[lane]), ar1 = ar0;
    int p0 = w * 2, p1 = w * 2 + 1;

#pragma unroll
    for (int k = 0; k < 32; k++) {
        const float* wrow = sW + k * 32 + lane;
        ULL w0 = dup2(wrow[0]);
        ULL w1 = dup2(wrow[1024]);
        ULL w2 = dup2(wrow[2048]);
        ULL w3 = dup2(wrow[3072]);
        ULL w4 = dup2(wrow[4096]);
        ULL w5 = dup2(wrow[5120]);
        ULL w6 = dup2(wrow[6144]);
        ULL w7 = dup2(wrow[7168]);
        const ULL* inrow = (const ULL*)(sInF + k * 132);
        ULL x0 = inrow[p0],      x1 = inrow[p1];
        ULL a0 = inrow[16 + p0], a1 = inrow[16 + p1];
        ULL h0 = inrow[32 + p0], h1 = inrow[32 + p1];
        ULL g0 = inrow[48 + p0], g1 = inrow[48 + p1];
        az0 = fma2(x0, w0, az0); az0 = fma2(a0, w1, az0);
        az0 = fma2(h0, w2, az0); az0 = fma2(g0, w3, az0);
        az1 = fma2(x1, w0, az1); az1 = fma2(a1, w1, az1);
        az1 = fma2(h1, w2, az1); az1 = fma2(g1, w3, az1);
        ar0 = fma2(x0, w4, ar0); ar0 = fma2(a0, w5, ar0);
        ar0 = fma2(h0, w6, ar0); ar0 = fma2(g0, w7, ar0);
        ar1 = fma2(x1, w4, ar1); ar1 = fma2(a1, w5, ar1);
        ar1 = fma2(h1, w6, ar1); ar1 = fma2(g1, w7, ar1);
    }

    float zp[4] = {lo2(az0), hi2(az0), lo2(az1), hi2(az1)};
    float rp[4] = {lo2(ar0), hi2(ar0), lo2(ar1), hi2(ar1)};
#pragma unroll
    for (int i = 0; i < 4; i++) {
        size_t b = (size_t)(nbase + i) * FH + lane;
        float z = 1.f / (1.f + __expf(-zp[i]));
        float r = 1.f / (1.f + __expf(-rp[i]));
        float hv = sInF[lane * 132 + 64 + (w * 2 + (i >> 1)) * 2 + (i & 1)];
        float hr = hv * r;
        g_Z[b]    = z;
        g_HR[b]   = hr;
        g_hr16[b] = __float2half_rn(hr);
    }
}

// ---------------- out GEMM: 4 nodes per warp, f32x2 ----------------
__global__ void __launch_bounds__(256) out_kernel(
    const float* __restrict__ x, const float* __restrict__ H,
    const float* __restrict__ Wxh, const float* __restrict__ bxh,
    const float* __restrict__ Whh, const float* __restrict__ bhh,
    const float* __restrict__ lw, const float* __restrict__ lb,
    float* __restrict__ out, int out_size) {
    __shared__ float sW[4 * 1024];         // [Wxh0, -Wxh1, Whh0, -Whh1]
    __shared__ __align__(16) float sInF[32 * 132];
    __shared__ float sbh[32];
    __shared__ float slw[128];
    __shared__ float slb[4];

    for (int i = threadIdx.x; i < 4 * 1024; i += blockDim.x) {
        int m = i >> 10;
        int r = i & 1023;
        const float* Wp = (m < 2) ? Wxh : Whh;
        float v = Wp[(m & 1) * 1024 + r];
        sW[i] = (m & 1) ? -v : v;
    }
    if (threadIdx.x < 32) sbh[threadIdx.x] = bxh[threadIdx.x] + bhh[threadIdx.x];
    if (threadIdx.x < 128) slw[threadIdx.x] = lw[threadIdx.x];
    if (threadIdx.x < 4) slb[threadIdx.x] = lb[threadIdx.x];
    __syncthreads();

    int w = threadIdx.x >> 5;
    int lane = threadIdx.x & 31;
    int nbase = blockIdx.x * 32 + w * 4;

#pragma unroll
    for (int i = 0; i < 4; i++) {
        size_t b = (size_t)(nbase + i) * FH + lane;
        int off = lane * 132 + (w * 2 + (i >> 1)) * 2 + (i & 1);
        sInF[off]      = x[b];
        sInF[off + 32] = g_aggx[b];
        sInF[off + 64] = g_HR[b];
        sInF[off + 96] = g_agghr[b];
    }
    __syncwarp();

    ULL a0acc = dup2(sbh[lane]), a1acc = a0acc;
    int p0 = w * 2, p1 = w * 2 + 1;

#pragma unroll
    for (int k = 0; k < 32; k++) {
        const float* wrow = sW + k * 32 + lane;
        ULL w0 = dup2(wrow[0]);
        ULL w1 = dup2(wrow[1024]);
        ULL w2 = dup2(wrow[2048]);
        ULL w3 = dup2(wrow[3072]);
        const ULL* inrow = (const ULL*)(sInF + k * 132);
        ULL x0 = inrow[p0],      x1 = inrow[p1];
        ULL a0 = inrow[16 + p0], a1 = inrow[16 + p1];
        ULL h0 = inrow[32 + p0], h1 = inrow[32 + p1];
        ULL g0 = inrow[48 + p0], g1 = inrow[48 + p1];
        a0acc = fma2(x0, w0, a0acc); a0acc = fma2(a0, w1, a0acc);
        a0acc = fma2(h0, w2, a0acc); a0acc = fma2(g0, w3, a0acc);
        a1acc = fma2(x1, w0, a1acc); a1acc = fma2(a1, w1, a1acc);
        a1acc = fma2(h1, w2, a1acc); a1acc = fma2(g1, w3, a1acc);
    }

    float ap[4] = {lo2(a0acc), hi2(a0acc), lo2(a1acc), hi2(a1acc)};
#pragma unroll
    for (int i = 0; i < 4; i++) {
        int node = nbase + i;
        size_t b = (size_t)node * FH + lane;
        float ht = tanhf(ap[i]);
        float z = g_Z[b];
        float hval = z * H[b] + (1.f - z) * ht;

        long long hidx = (long long)NN * 4 + (long long)b;
        if (hidx < (long long)out_size) out[hidx] = hval;

        float rh = fmaxf(hval, 0.f);
#pragma unroll
        for (int j = 0; j < 4; j++) {
            float s = rh * slw[lane * 4 + j];
#pragma unroll
            for (int off = 16; off; off >>= 1) s += __shfl_xor_sync(0xffffffffu, s, off);
            if (lane == 0 && (long long)node * 4 + j < (long long)out_size)
                out[(size_t)node * 4 + j] = s + slb[j];
        }
    }
}

// ---------------- launch ----------------
extern "C" void kernel_launch(void* const* d_in, const int* in_sizes, int n_in,
                              void* d_out, int out_size) {
    const float* x   = (const float*)d_in[0];
    const void*  ei  = d_in[1];
    const float* ew  = (const float*)d_in[2];
    const float* H   = (const float*)d_in[3];
    const float* Wxz = (const float*)d_in[4];
    const float* bxz = (const float*)d_in[5];
    const float* Whz = (const float*)d_in[6];
    const float* bhz = (const float*)d_in[7];
    const float* Wxr = (const float*)d_in[8];
    const float* bxr = (const float*)d_in[9];
    const float* Whr = (const float*)d_in[10];
    const float* bhr = (const float*)d_in[11];
    const float* Wxh = (const float*)d_in[12];
    const float* bxh = (const float*)d_in[13];
    const float* Whh = (const float*)d_in[14];
    const float* bhh = (const float*)d_in[15];
    const float* lw  = (const float*)d_in[16];
    const float* lb  = (const float*)d_in[17];
    float* out = (float*)d_out;

    static int smem_set = 0;
    if (!smem_set) {
        cudaFuncSetAttribute(gate_kernel, cudaFuncAttributeMaxDynamicSharedMemorySize,
                             GATE_SMEM_FLOATS * 4);
        smem_set = 1;
    }

    init_kernel<<<(NN * FH + 255) / 256, 256>>>(ei, x, H);
    passA_kernel<<<(EE + 255) / 256, 256>>>(ei, ew);
    dinv_kernel<<<(NN + 255) / 256, 256>>>();
    scatter_xh_kernel<<<(EE * 4 + 255) / 256, 256>>>(ew);
    gate_kernel<<<(NN + 31) / 32, 256, GATE_SMEM_FLOATS * 4>>>(
        x, H, Wxz, bxz, Whz, bhz, Wxr, bxr, Whr, bhr);
    scatter_hr_kernel<<<(EE * 4 + 255) / 256, 256>>>();
    out_kernel<<<(NN + 31) / 32, 256>>>(x, H, Wxh, bxh, Whh, bhh, lw, lb, out, out_size);
}